// round 6
// baseline (speedup 1.0000x reference)
#include <cuda_runtime.h>
#include <cstdint>

// Problem constants (fixed by the benchmark's setup_inputs).
#define BS      32
#define M       256
#define N       512
#define ITERS   1000
#define ALPHA   0.02f
#define BETA    0.02f

#define CLUSTER 4
#define ROWS    (M / CLUSTER)      // 64 rows of A per CTA
#define THREADS 512

// Dynamic SMEM layout (float offsets)
#define OFF_AS  0                        // A slice: ROWS x N       = 32768 floats
#define OFF_ZS  (ROWS * N)               // zscratch: 4 x N          =  2048
#define OFF_ZP  (OFF_ZS + 4 * N)         // zpart (double buffer): 2 x N = 1024
#define OFF_W   (OFF_ZP + 2 * N)         // wfull: N                 =   512
#define OFF_U   (OFF_W + N)              // u slice: ROWS            =    64
#define OFF_B   (OFF_U + ROWS)           // b slice: ROWS            =    64
#define SMEM_FLOATS (OFF_B + ROWS)
#define SMEM_BYTES  (SMEM_FLOATS * 4)    // 145,920 bytes

__device__ __forceinline__ uint32_t smem_u32(const void* p) {
    uint32_t a;
    asm("{ .reg .u64 t; cvta.to.shared.u64 t, %1; cvt.u32.u64 %0, t; }"
        : "=r"(a) : "l"(p));
    return a;
}

__device__ __forceinline__ uint32_t mapa_rank(uint32_t addr, uint32_t rank) {
    uint32_t o;
    asm("mapa.shared::cluster.u32 %0, %1, %2;" : "=r"(o) : "r"(addr), "r"(rank));
    return o;
}

__device__ __forceinline__ float ldsc_f32(uint32_t addr) {
    float v;
    asm volatile("ld.shared::cluster.f32 %0, [%1];" : "=f"(v) : "r"(addr) : "memory");
    return v;
}

__device__ __forceinline__ void cluster_sync_() {
    asm volatile("barrier.cluster.arrive.aligned;" ::: "memory");
    asm volatile("barrier.cluster.wait.aligned;" ::: "memory");
}

extern __shared__ float smem[];

__global__ void __cluster_dims__(CLUSTER, 1, 1) __launch_bounds__(THREADS, 1)
pdhg_kernel(const float* __restrict__ A, const float* __restrict__ b,
            float* __restrict__ out)
{
    const int tid   = threadIdx.x;
    const int batch = blockIdx.x / CLUSTER;
    const int rank  = blockIdx.x % CLUSTER;

    float4* As4 = reinterpret_cast<float4*>(smem + OFF_AS);

    // ---- Load A slice (64 x 512 f32, coalesced LDG.128 -> STS.128) ----
    {
        const float4* Ag = reinterpret_cast<const float4*>(
            A + (size_t)batch * (M * N) + (size_t)rank * (ROWS * N));
        #pragma unroll
        for (int i = 0; i < (ROWS * N / 4) / THREADS; ++i)
            As4[i * THREADS + tid] = Ag[i * THREADS + tid];
    }
    // ---- Load b slice, init u = 0 ----
    if (tid < ROWS) {
        smem[OFF_B + tid] = b[batch * M + rank * ROWS + tid];
        smem[OFF_U + tid] = 0.0f;
    }

    // Each thread owns column `tid` of the (redundantly replicated) x vector.
    float xreg = 0.0f;

    // Remote zpart base addresses for the 4 cluster ranks.
    const uint32_t zp_local = smem_u32(smem + OFF_ZP);
    uint32_t zp_r[CLUSTER];
    #pragma unroll
    for (int p = 0; p < CLUSTER; ++p) zp_r[p] = mapa_rank(zp_local, p);

    __syncthreads();

    const int tcol = tid & 127;   // float4 column group 0..127 (cols 4*tcol..4*tcol+3)
    const int s    = tid >> 7;    // row group 0..3 (rows 16s..16s+15)
    const int lane = tid & 31;
    const int wrp  = tid >> 5;    // warp 0..15 -> rows 4*wrp..4*wrp+3

    for (int it = 0; it < ITERS; ++it) {
        const int buf = it & 1;

        // ================= Pass 1: zpart[n] = sum_m A[m][n] * u[m] ========
        {
            float4 acc = make_float4(0.f, 0.f, 0.f, 0.f);
            #pragma unroll
            for (int i = 0; i < 16; ++i) {
                const int m = (s << 4) + i;
                const float um = smem[OFF_U + m];        // broadcast LDS
                const float4 a = As4[m * 128 + tcol];    // conflict-free LDS.128
                acc.x = fmaf(a.x, um, acc.x);
                acc.y = fmaf(a.y, um, acc.y);
                acc.z = fmaf(a.z, um, acc.z);
                acc.w = fmaf(a.w, um, acc.w);
            }
            reinterpret_cast<float4*>(smem + OFF_ZS)[s * 128 + tcol] = acc;
        }
        __syncthreads();
        {
            const float z = smem[OFF_ZS +          tid] +
                            smem[OFF_ZS + 1 * N + tid] +
                            smem[OFF_ZS + 2 * N + tid] +
                            smem[OFF_ZS + 3 * N + tid];
            smem[OFF_ZP + buf * N + tid] = z;
        }

        cluster_sync_();   // publishes zpart cluster-wide (release/acquire)

        // ====== x update (computed redundantly in all 4 CTAs) =============
        {
            float ztot = 0.0f;
            const uint32_t off = (uint32_t)(buf * N + tid) * 4u;
            #pragma unroll
            for (int p = 0; p < CLUSTER; ++p)
                ztot += ldsc_f32(zp_r[p] + off);

            const float v  = fmaf(-ALPHA, ztot, xreg);
            const float xn = fmaxf(v - ALPHA, 0.0f) - fmaxf(-v - ALPHA, 0.0f);
            smem[OFF_W + tid] = 2.0f * xn - xreg;
            xreg = xn;
        }
        __syncthreads();

        // ================= Pass 2: u[m] += beta*(A[m]·w - b[m]) ===========
        {
            const float4* W4 = reinterpret_cast<const float4*>(smem + OFF_W);
            const float4 w0 = W4[lane];
            const float4 w1 = W4[lane + 32];
            const float4 w2 = W4[lane + 64];
            const float4 w3 = W4[lane + 96];

            #pragma unroll
            for (int r = 0; r < 4; ++r) {
                const int m = (wrp << 2) + r;
                const float4* ar = As4 + m * 128;
                const float4 a0 = ar[lane];
                const float4 a1 = ar[lane + 32];
                const float4 a2 = ar[lane + 64];
                const float4 a3 = ar[lane + 96];

                float y = a0.x * w0.x;
                y = fmaf(a0.y, w0.y, y); y = fmaf(a0.z, w0.z, y); y = fmaf(a0.w, w0.w, y);
                y = fmaf(a1.x, w1.x, y); y = fmaf(a1.y, w1.y, y);
                y = fmaf(a1.z, w1.z, y); y = fmaf(a1.w, w1.w, y);
                y = fmaf(a2.x, w2.x, y); y = fmaf(a2.y, w2.y, y);
                y = fmaf(a2.z, w2.z, y); y = fmaf(a2.w, w2.w, y);
                y = fmaf(a3.x, w3.x, y); y = fmaf(a3.y, w3.y, y);
                y = fmaf(a3.z, w3.z, y); y = fmaf(a3.w, w3.w, y);

                #pragma unroll
                for (int off = 16; off > 0; off >>= 1)
                    y += __shfl_xor_sync(0xffffffffu, y, off);

                if (lane == 0)
                    smem[OFF_U + m] = fmaf(BETA, y - smem[OFF_B + m], smem[OFF_U + m]);
            }
        }
        __syncthreads();   // u must be visible to next pass 1
    }

    // ---- Output: rank-0 CTA writes its batch's x (all CTAs hold identical x) ----
    if (rank == 0)
        out[batch * N + tid] = xreg;
}

extern "C" void kernel_launch(void* const* d_in, const int* in_sizes, int n_in,
                              void* d_out, int out_size)
{
    (void)in_sizes; (void)n_in; (void)out_size;
    const float* A = (const float*)d_in[0];
    const float* b = (const float*)d_in[1];
    float* out = (float*)d_out;

    cudaFuncSetAttribute(pdhg_kernel,
                         cudaFuncAttributeMaxDynamicSharedMemorySize, SMEM_BYTES);
    pdhg_kernel<<<BS * CLUSTER, THREADS, SMEM_BYTES>>>(A, b, out);
}

// round 7
// speedup vs baseline: 1.5133x; 1.5133x over previous
#include <cuda_runtime.h>
#include <cstdint>

// Problem constants (fixed by the benchmark's setup_inputs).
#define BS      32
#define M       256
#define N       512
#define ITERS   1000
#define ALPHA   0.02f
#define BETA    0.02f

#define CLUSTER 4
#define ROWS    (M / CLUSTER)      // 64 rows of A per CTA
#define THREADS 512

__device__ __forceinline__ uint32_t smem_u32(const void* p) {
    uint32_t a;
    asm("{ .reg .u64 t; cvta.to.shared.u64 t, %1; cvt.u32.u64 %0, t; }"
        : "=r"(a) : "l"(p));
    return a;
}

__device__ __forceinline__ uint32_t mapa_rank(uint32_t addr, uint32_t rank) {
    uint32_t o;
    asm("mapa.shared::cluster.u32 %0, %1, %2;" : "=r"(o) : "r"(addr), "r"(rank));
    return o;
}

__device__ __forceinline__ float ldsc_f32(uint32_t addr) {
    float v;
    asm volatile("ld.shared::cluster.f32 %0, [%1];" : "=f"(v) : "r"(addr) : "memory");
    return v;
}

__device__ __forceinline__ void cluster_sync_() {
    asm volatile("barrier.cluster.arrive.aligned;" ::: "memory");
    asm volatile("barrier.cluster.wait.aligned;" ::: "memory");
}

// ---- packed f32x2 helpers (Blackwell FFMA2 via PTX) ----
__device__ __forceinline__ uint64_t pk2(float lo, float hi) {
    uint64_t r;
    asm("mov.b64 %0, {%1, %2};" : "=l"(r) : "f"(lo), "f"(hi));
    return r;
}
__device__ __forceinline__ void unpk2(uint64_t v, float& lo, float& hi) {
    asm("mov.b64 {%0, %1}, %2;" : "=f"(lo), "=f"(hi) : "l"(v));
}
__device__ __forceinline__ uint64_t fma2(uint64_t a, uint64_t b, uint64_t c) {
    uint64_t d;
    asm("fma.rn.f32x2 %0, %1, %2, %3;" : "=l"(d) : "l"(a), "l"(b), "l"(c));
    return d;
}

__global__ void __cluster_dims__(CLUSTER, 1, 1) __launch_bounds__(THREADS, 1)
pdhg_kernel(const float* __restrict__ A, const float* __restrict__ b,
            float* __restrict__ out)
{
    // Static SMEM: staging + exchange buffers only (A lives in registers).
    __shared__ float zs[16 * N];   // per-warp partial z: [warp][col]  (32 KB)
    __shared__ float zp[2 * N];    // published partial z (double buffered)
    __shared__ float wv[N];        // w = 2*x_new - x_old
    __shared__ float uv[ROWS];     // u slice
    __shared__ float bv[ROWS];     // b slice

    const int tid   = threadIdx.x;
    const int batch = blockIdx.x / CLUSTER;
    const int rank  = blockIdx.x % CLUSTER;
    const int lane  = tid & 31;
    const int wrp   = tid >> 5;    // 0..15 -> rows 4*wrp..4*wrp+3

    // ---- Load this thread's A chunk straight into registers (packed f32x2).
    // Thread (wrp, lane): rows m = 4*wrp + r (r=0..3),
    //                     float4 column groups g = lane + 32*c (c=0..3).
    uint64_t Apk[4][8];
    {
        const float4* Ag = reinterpret_cast<const float4*>(
            A + (size_t)batch * (M * N) + (size_t)rank * (ROWS * N));
        #pragma unroll
        for (int r = 0; r < 4; ++r) {
            const int m = (wrp << 2) + r;
            #pragma unroll
            for (int c = 0; c < 4; ++c) {
                const float4 v = Ag[m * 128 + lane + 32 * c];
                Apk[r][2 * c]     = pk2(v.x, v.y);
                Apk[r][2 * c + 1] = pk2(v.z, v.w);
            }
        }
    }

    if (tid < ROWS) {
        bv[tid] = b[batch * M + rank * ROWS + tid];
        uv[tid] = 0.0f;
    }

    float xreg = 0.0f;   // this thread owns column `tid` of the replicated x

    const uint32_t zp_local = smem_u32(zp);
    uint32_t zp_r[CLUSTER];
    #pragma unroll
    for (int p = 0; p < CLUSTER; ++p) zp_r[p] = mapa_rank(zp_local, p);

    __syncthreads();

    float4* zs4 = reinterpret_cast<float4*>(zs);
    const float4* W4 = reinterpret_cast<const float4*>(wv);

    for (int it = 0; it < ITERS; ++it) {
        const int buf = it & 1;

        // ========== Pass 1: per-warp partial z[n] = sum_{4 rows} A[m][n]*u[m]
        {
            uint64_t pz[8];
            #pragma unroll
            for (int j = 0; j < 8; ++j) pz[j] = 0ull;

            #pragma unroll
            for (int r = 0; r < 4; ++r) {
                const float um = uv[(wrp << 2) + r];   // broadcast LDS
                const uint64_t um2 = pk2(um, um);
                #pragma unroll
                for (int j = 0; j < 8; ++j)
                    pz[j] = fma2(Apk[r][j], um2, pz[j]);
            }
            // stage: zs[wrp][cols of group g] — conflict-free STS.128
            #pragma unroll
            for (int c = 0; c < 4; ++c) {
                float x0, y0, x1, y1;
                unpk2(pz[2 * c],     x0, y0);
                unpk2(pz[2 * c + 1], x1, y1);
                zs4[wrp * 128 + lane + 32 * c] = make_float4(x0, y0, x1, y1);
            }
        }
        __syncthreads();

        // 16-way cross-warp reduction: thread tid owns column tid
        {
            float z = 0.0f;
            #pragma unroll
            for (int w = 0; w < 16; ++w)
                z += zs[w * N + tid];
            zp[buf * N + tid] = z;
        }

        cluster_sync_();   // publish zp cluster-wide (release/acquire)

        // ========== x update (redundant in all 4 CTAs) ==========
        {
            const uint32_t off = (uint32_t)(buf * N + tid) * 4u;
            float z0 = ldsc_f32(zp_r[0] + off);
            float z1 = ldsc_f32(zp_r[1] + off);
            float z2 = ldsc_f32(zp_r[2] + off);
            float z3 = ldsc_f32(zp_r[3] + off);
            const float ztot = (z0 + z1) + (z2 + z3);

            const float v  = fmaf(-ALPHA, ztot, xreg);
            const float xn = fmaxf(v - ALPHA, 0.0f) - fmaxf(-v - ALPHA, 0.0f);
            wv[tid] = 2.0f * xn - xreg;
            xreg = xn;
        }
        __syncthreads();

        // ========== Pass 2: u[m] += beta * (A[m]·w - b[m]) ==========
        {
            uint64_t wpk[8];
            #pragma unroll
            for (int c = 0; c < 4; ++c) {
                const float4 wq = W4[lane + 32 * c];
                wpk[2 * c]     = pk2(wq.x, wq.y);
                wpk[2 * c + 1] = pk2(wq.z, wq.w);
            }

            #pragma unroll
            for (int r = 0; r < 4; ++r) {
                uint64_t acc = 0ull;
                #pragma unroll
                for (int j = 0; j < 8; ++j)
                    acc = fma2(Apk[r][j], wpk[j], acc);
                float alo, ahi;
                unpk2(acc, alo, ahi);
                float y = alo + ahi;

                #pragma unroll
                for (int off = 16; off > 0; off >>= 1)
                    y += __shfl_xor_sync(0xffffffffu, y, off);

                if (lane == 0) {
                    const int m = (wrp << 2) + r;
                    uv[m] = fmaf(BETA, y - bv[m], uv[m]);
                }
            }
        }
        __syncthreads();   // u visible to next pass 1
    }

    // ---- Output: rank-0 CTA writes its batch's x ----
    if (rank == 0)
        out[batch * N + tid] = xreg;
}

extern "C" void kernel_launch(void* const* d_in, const int* in_sizes, int n_in,
                              void* d_out, int out_size)
{
    (void)in_sizes; (void)n_in; (void)out_size;
    const float* A = (const float*)d_in[0];
    const float* b = (const float*)d_in[1];
    float* out = (float*)d_out;

    pdhg_kernel<<<BS * CLUSTER, THREADS>>>(A, b, out);
}

// round 11
// speedup vs baseline: 1.8660x; 1.2331x over previous
#include <cuda_runtime.h>
#include <cstdint>

// Problem constants (fixed by the benchmark's setup_inputs).
#define BS      32
#define M       256
#define N       512
#define ITERS   1000
#define ALPHA   0.02f
#define BETA    0.02f

#define CLUSTER 4
#define ROWS    (M / CLUSTER)      // 64 rows of A per CTA
#define THREADS 512
#define EXPECT_BYTES (CLUSTER * N * 4)   // 8192 bytes per exchange phase

__device__ __forceinline__ uint32_t smem_u32(const void* p) {
    uint32_t a;
    asm("{ .reg .u64 t; cvta.to.shared.u64 t, %1; cvt.u32.u64 %0, t; }"
        : "=r"(a) : "l"(p));
    return a;
}

__device__ __forceinline__ uint32_t mapa_rank(uint32_t addr, uint32_t rank) {
    uint32_t o;
    asm("mapa.shared::cluster.u32 %0, %1, %2;" : "=r"(o) : "r"(addr), "r"(rank));
    return o;
}

__device__ __forceinline__ void cluster_sync_() {
    asm volatile("barrier.cluster.arrive.aligned;" ::: "memory");
    asm volatile("barrier.cluster.wait.aligned;" ::: "memory");
}

// Remote SMEM store with mbarrier tx-completion (Hopper+ st.async).
__device__ __forceinline__ void st_async_f32(uint32_t raddr, float v, uint32_t rmbar) {
    asm volatile(
        "st.async.shared::cluster.mbarrier::complete_tx::bytes.f32 [%0], %1, [%2];"
        :: "r"(raddr), "f"(v), "r"(rmbar) : "memory");
}

__device__ __forceinline__ void mbar_init(uint32_t addr, uint32_t count) {
    asm volatile("mbarrier.init.shared.b64 [%0], %1;" :: "r"(addr), "r"(count) : "memory");
}

__device__ __forceinline__ void mbar_arrive_expect_tx(uint32_t addr, uint32_t bytes) {
    asm volatile("mbarrier.arrive.expect_tx.shared.b64 _, [%0], %1;"
                 :: "r"(addr), "r"(bytes) : "memory");
}

// Cluster-scope acquire wait (following LDS reads must see remote st.async data).
__device__ __forceinline__ void mbar_wait(uint32_t addr, uint32_t parity) {
    uint32_t done;
    asm volatile(
        "{\n\t.reg .pred p;\n\t"
        "mbarrier.try_wait.parity.acquire.cluster.shared::cta.b64 p, [%1], %2, 0x989680;\n\t"
        "selp.b32 %0, 1, 0, p;\n\t}"
        : "=r"(done) : "r"(addr), "r"(parity) : "memory");
    while (!done) {
        asm volatile(
            "{\n\t.reg .pred p;\n\t"
            "mbarrier.try_wait.parity.acquire.cluster.shared::cta.b64 p, [%1], %2, 0x989680;\n\t"
            "selp.b32 %0, 1, 0, p;\n\t}"
            : "=r"(done) : "r"(addr), "r"(parity) : "memory");
    }
}

// ---- packed f32x2 helpers (Blackwell FFMA2 via PTX) ----
__device__ __forceinline__ uint64_t pk2(float lo, float hi) {
    uint64_t r;
    asm("mov.b64 %0, {%1, %2};" : "=l"(r) : "f"(lo), "f"(hi));
    return r;
}
__device__ __forceinline__ void unpk2(uint64_t v, float& lo, float& hi) {
    asm("mov.b64 {%0, %1}, %2;" : "=f"(lo), "=f"(hi) : "l"(v));
}
__device__ __forceinline__ uint64_t fma2(uint64_t a, uint64_t b, uint64_t c) {
    uint64_t d;
    asm("fma.rn.f32x2 %0, %1, %2, %3;" : "=l"(d) : "l"(a), "l"(b), "l"(c));
    return d;
}

__global__ void __cluster_dims__(CLUSTER, 1, 1) __launch_bounds__(THREADS, 1)
pdhg_kernel(const float* __restrict__ A, const float* __restrict__ b,
            float* __restrict__ out)
{
    __shared__ float zs[16 * N];                 // per-warp partial z  (32 KB)
    __shared__ float zin[2][CLUSTER][N];         // incoming partials   (16 KB)
    __shared__ float wv[N];                      // w = 2*x_new - x_old
    __shared__ __align__(8) unsigned long long mbar[2];

    const int tid   = threadIdx.x;
    const int batch = blockIdx.x / CLUSTER;
    const int rank  = blockIdx.x % CLUSTER;
    const int lane  = tid & 31;
    const int wrp   = tid >> 5;                  // 0..15 -> rows 4*wrp..4*wrp+3

    // ---- A chunk straight into registers (packed f32x2).
    // Thread (wrp, lane): rows m = 4*wrp + r, float4 col groups lane + 32*c.
    uint64_t Apk[4][8];
    {
        const float4* Ag = reinterpret_cast<const float4*>(
            A + (size_t)batch * (M * N) + (size_t)rank * (ROWS * N));
        #pragma unroll
        for (int r = 0; r < 4; ++r) {
            const int m = (wrp << 2) + r;
            #pragma unroll
            for (int c = 0; c < 4; ++c) {
                const float4 v = Ag[m * 128 + lane + 32 * c];
                Apk[r][2 * c]     = pk2(v.x, v.y);
                Apk[r][2 * c + 1] = pk2(v.z, v.w);
            }
        }
    }

    // ---- u, b in registers (replicated across the warp's lanes) ----
    float ureg[4], breg[4];
    #pragma unroll
    for (int r = 0; r < 4; ++r) {
        ureg[r] = 0.0f;
        breg[r] = b[batch * M + rank * ROWS + (wrp << 2) + r];
    }

    float xreg = 0.0f;   // this thread owns column `tid` of the replicated x

    // ---- mbarrier + remote address setup ----
    const uint32_t mbar_base = smem_u32(mbar);
    const uint32_t zin_base  = smem_u32(zin);
    if (tid == 0) {
        mbar_init(mbar_base, 1);
        mbar_init(mbar_base + 8, 1);
    }
    // Remote destinations: rank p's zin[buf][myrank][tid] and mbar[buf].
    uint32_t zin_r[CLUSTER], mbar_r[CLUSTER];
    #pragma unroll
    for (int p = 0; p < CLUSTER; ++p) {
        zin_r[p]  = mapa_rank(zin_base, p) + ((uint32_t)(rank * N + tid) * 4u);
        mbar_r[p] = mapa_rank(mbar_base, p);
    }
    __syncthreads();
    cluster_sync_();   // all ranks' mbarriers initialized before any st.async

    float4* zs4 = reinterpret_cast<float4*>(zs);
    const float4* W4 = reinterpret_cast<const float4*>(wv);
    uint32_t parity[2] = {0u, 0u};

    for (int it = 0; it < ITERS; ++it) {
        const int buf = it & 1;
        const uint32_t buf_off = (uint32_t)(buf * CLUSTER * N) * 4u;

        if (tid == 0)
            mbar_arrive_expect_tx(mbar_base + 8u * buf, EXPECT_BYTES);

        // ========== Pass 1: per-warp partial z[n] = sum_{4 rows} A[m][n]*u[m]
        {
            uint64_t pz[8];
            #pragma unroll
            for (int j = 0; j < 8; ++j) pz[j] = 0ull;

            #pragma unroll
            for (int r = 0; r < 4; ++r) {
                const uint64_t um2 = pk2(ureg[r], ureg[r]);
                #pragma unroll
                for (int j = 0; j < 8; ++j)
                    pz[j] = fma2(Apk[r][j], um2, pz[j]);
            }
            #pragma unroll
            for (int c = 0; c < 4; ++c) {
                float x0, y0, x1, y1;
                unpk2(pz[2 * c],     x0, y0);
                unpk2(pz[2 * c + 1], x1, y1);
                zs4[wrp * 128 + lane + 32 * c] = make_float4(x0, y0, x1, y1);
            }
        }
        __syncthreads();

        // 16-way cross-warp reduction, then push partial to all 4 ranks.
        {
            float z0 = 0.f, z1 = 0.f;
            #pragma unroll
            for (int w = 0; w < 16; w += 2) {
                z0 += zs[w * N + tid];
                z1 += zs[(w + 1) * N + tid];
            }
            const float z = z0 + z1;
            #pragma unroll
            for (int p = 0; p < CLUSTER; ++p)
                st_async_f32(zin_r[p] + buf_off, z, mbar_r[p] + 8u * buf);
        }

        // ========== Wait for all 4 partials, then x update (local LDS) =====
        mbar_wait(mbar_base + 8u * buf, parity[buf]);
        parity[buf] ^= 1u;
        {
            const float* zb = &zin[buf][0][0];
            const float ztot = (zb[tid] + zb[N + tid]) +
                               (zb[2 * N + tid] + zb[3 * N + tid]);

            const float v  = fmaf(-ALPHA, ztot, xreg);
            const float xn = fmaxf(v - ALPHA, 0.0f) - fmaxf(-v - ALPHA, 0.0f);
            wv[tid] = 2.0f * xn - xreg;
            xreg = xn;
        }
        __syncthreads();

        // ========== Pass 2: u[m] += beta * (A[m]·w - b[m])  (u in regs) ====
        {
            uint64_t wpk[8];
            #pragma unroll
            for (int c = 0; c < 4; ++c) {
                const float4 wq = W4[lane + 32 * c];
                wpk[2 * c]     = pk2(wq.x, wq.y);
                wpk[2 * c + 1] = pk2(wq.z, wq.w);
            }

            #pragma unroll
            for (int r = 0; r < 4; ++r) {
                uint64_t acc = 0ull;
                #pragma unroll
                for (int j = 0; j < 8; ++j)
                    acc = fma2(Apk[r][j], wpk[j], acc);
                float alo, ahi;
                unpk2(acc, alo, ahi);
                float y = alo + ahi;

                #pragma unroll
                for (int off = 16; off > 0; off >>= 1)
                    y += __shfl_xor_sync(0xffffffffu, y, off);

                ureg[r] = fmaf(BETA, y - breg[r], ureg[r]);   // all lanes
            }
        }
        // no trailing sync: next pass1 uses only warp-local ureg; zs rewrite
        // is ordered by the wv __syncthreads above.
    }

    // ---- Output: rank-0 CTA writes its batch's x ----
    if (rank == 0)
        out[batch * N + tid] = xreg;
}

extern "C" void kernel_launch(void* const* d_in, const int* in_sizes, int n_in,
                              void* d_out, int out_size)
{
    (void)in_sizes; (void)n_in; (void)out_size;
    const float* A = (const float*)d_in[0];
    const float* b = (const float*)d_in[1];
    float* out = (float*)d_out;

    pdhg_kernel<<<BS * CLUSTER, THREADS>>>(A, b, out);
}